// round 1
// baseline (speedup 1.0000x reference)
#include <cuda_runtime.h>
#include <cstdint>

#define BM 128
#define BN 128
#define BK 32
#define NTHREADS 256

__device__ __forceinline__ uint32_t f2tf32(float x) {
    uint32_t r;
    asm("cvt.rna.tf32.f32 %0, %1;" : "=r"(r) : "f"(x));
    return r;
}

__device__ __forceinline__ void mma_tf32(float c[4],
                                         uint32_t a0, uint32_t a1, uint32_t a2, uint32_t a3,
                                         uint32_t b0, uint32_t b1) {
    asm volatile(
        "mma.sync.aligned.m16n8k8.row.col.f32.tf32.tf32.f32 "
        "{%0,%1,%2,%3}, {%4,%5,%6,%7}, {%8,%9}, {%0,%1,%2,%3};\n"
        : "+f"(c[0]), "+f"(c[1]), "+f"(c[2]), "+f"(c[3])
        : "r"(a0), "r"(a1), "r"(a2), "r"(a3), "r"(b0), "r"(b1));
}

__device__ __forceinline__ void ldg_tile(const float* __restrict__ Ag,
                                         const float* __restrict__ Bg,
                                         int kt, float4 ra[4], float4 rb[4]) {
    const int K = 4096;
    #pragma unroll
    for (int i = 0; i < 4; ++i) {
        ra[i] = *(const float4*)(Ag + (size_t)(i * 32) * K + (size_t)kt * BK);
        rb[i] = *(const float4*)(Bg + (size_t)(i * 32) * K + (size_t)kt * BK);
    }
}

__device__ __forceinline__ void sts_tile(uint32_t* __restrict__ As,
                                         uint32_t* __restrict__ Bs,
                                         const float4 ra[4], const float4 rb[4],
                                         int mrow, int k4) {
    #pragma unroll
    for (int i = 0; i < 4; ++i) {
        int m = mrow + i * 32;
        int idx = m * BK + (k4 ^ ((m & 7) * 4));   // XOR swizzle, 16B aligned
        uint4 va;
        va.x = f2tf32(ra[i].x); va.y = f2tf32(ra[i].y);
        va.z = f2tf32(ra[i].z); va.w = f2tf32(ra[i].w);
        *(uint4*)(As + idx) = va;
        uint4 vb;
        vb.x = f2tf32(rb[i].x); vb.y = f2tf32(rb[i].y);
        vb.z = f2tf32(rb[i].z); vb.w = f2tf32(rb[i].w);
        *(uint4*)(Bs + idx) = vb;
    }
}

__global__ void __launch_bounds__(NTHREADS)
bsl_tf32_kernel(const float* __restrict__ X, const float* __restrict__ W,
                const float* __restrict__ Bias, float* __restrict__ Y, int M) {
    const int K = 4096, N = 4096;
    extern __shared__ uint32_t smem[];
    uint32_t* As = smem;                 // [2][BM*BK]
    uint32_t* Bs = smem + 2 * BM * BK;   // [2][BN*BK]

    const int tid  = threadIdx.x;
    const int lane = tid & 31;
    const int warp = tid >> 5;
    const int wm   = warp >> 2;          // 0..1  (M direction)
    const int wn   = warp & 3;           // 0..3  (N direction)
    const int row  = lane >> 2;          // 0..7
    const int col  = lane & 3;           // 0..3

    const int bm = blockIdx.y * BM;
    const int bn = blockIdx.x * BN;

    const int mrow = tid >> 3;           // 0..31
    const int k4   = (tid & 7) * 4;      // 0,4,...,28

    const float* Ag = X + (size_t)(bm + mrow) * K + k4;
    const float* Bg = W + (size_t)(bn + mrow) * K + k4;

    float acc[4][4][4];
    #pragma unroll
    for (int mt = 0; mt < 4; ++mt)
        #pragma unroll
        for (int nt = 0; nt < 4; ++nt)
            #pragma unroll
            for (int j = 0; j < 4; ++j) acc[mt][nt][j] = 0.0f;

    float4 ra[4], rb[4];
    const int nk = K / BK;               // 128

    // Prologue: fill buffer 0
    ldg_tile(Ag, Bg, 0, ra, rb);
    sts_tile(As, Bs, ra, rb, mrow, k4);
    __syncthreads();

    int cur = 0;
    for (int t = 0; t < nk; ++t) {
        if (t + 1 < nk) ldg_tile(Ag, Bg, t + 1, ra, rb);

        const uint32_t* Ac = As + cur * (BM * BK);
        const uint32_t* Bc = Bs + cur * (BN * BK);
        #pragma unroll
        for (int kk = 0; kk < 4; ++kk) {
            uint32_t a[4][4], b[4][2];
            const int s  = row * 4;
            const int i0 = (kk * 8 + col) ^ s;
            const int i1 = (kk * 8 + 4 + col) ^ s;
            #pragma unroll
            for (int mt = 0; mt < 4; ++mt) {
                const int m0 = wm * 64 + mt * 16 + row;
                const uint32_t* p0 = Ac + m0 * BK;
                const uint32_t* p1 = p0 + 8 * BK;
                a[mt][0] = p0[i0]; a[mt][1] = p1[i0];
                a[mt][2] = p0[i1]; a[mt][3] = p1[i1];
            }
            #pragma unroll
            for (int nt = 0; nt < 4; ++nt) {
                const int n0 = wn * 32 + nt * 8 + row;
                const uint32_t* q = Bc + n0 * BK;
                b[nt][0] = q[i0];
                b[nt][1] = q[i1];
            }
            #pragma unroll
            for (int mt = 0; mt < 4; ++mt)
                #pragma unroll
                for (int nt = 0; nt < 4; ++nt)
                    mma_tf32(acc[mt][nt],
                             a[mt][0], a[mt][1], a[mt][2], a[mt][3],
                             b[nt][0], b[nt][1]);
        }

        if (t + 1 < nk)
            sts_tile(As + (cur ^ 1) * (BM * BK), Bs + (cur ^ 1) * (BN * BK),
                     ra, rb, mrow, k4);
        __syncthreads();
        cur ^= 1;
    }

    // Epilogue: add bias, write fp32 output
    #pragma unroll
    for (int nt = 0; nt < 4; ++nt) {
        const int gn = bn + wn * 32 + nt * 8 + col * 2;
        const float2 bb = *(const float2*)(Bias + gn);
        #pragma unroll
        for (int mt = 0; mt < 4; ++mt) {
            const int gm = bm + wm * 64 + mt * 16 + row;
            float2 v0, v1;
            v0.x = acc[mt][nt][0] + bb.x; v0.y = acc[mt][nt][1] + bb.y;
            v1.x = acc[mt][nt][2] + bb.x; v1.y = acc[mt][nt][3] + bb.y;
            *(float2*)(Y + (size_t)gm * N + gn)       = v0;
            *(float2*)(Y + (size_t)(gm + 8) * N + gn) = v1;
        }
    }
}

extern "C" void kernel_launch(void* const* d_in, const int* in_sizes, int n_in,
                              void* d_out, int out_size) {
    const float* X    = (const float*)d_in[0];   // [M, 4096]
    const float* W    = (const float*)d_in[1];   // [4096, 4096]
    const float* Bias = (const float*)d_in[2];   // [4096]
    float* Y = (float*)d_out;

    const int K = 4096;
    const int N = in_sizes[2];                   // 4096
    const int M = in_sizes[0] / K;               // 8192

    const size_t smem_bytes = 2 * (size_t)(BM * BK + BN * BK) * sizeof(uint32_t); // 64 KB
    cudaFuncSetAttribute(bsl_tf32_kernel,
                         cudaFuncAttributeMaxDynamicSharedMemorySize,
                         (int)smem_bytes);

    dim3 grid(N / BN, M / BM);   // (32, 64): N fast -> wave covers all N-tiles, L2-friendly
    bsl_tf32_kernel<<<grid, NTHREADS, smem_bytes>>>(X, W, Bias, Y, M);
}

// round 5
// speedup vs baseline: 1.3369x; 1.3369x over previous
#include <cuda_runtime.h>
#include <cstdint>

#define BM 256
#define BN 128
#define BK 32
#define NT 512

static __device__ __forceinline__ uint32_t s2u(const void* p) {
    uint32_t a;
    asm("{ .reg .u64 t; cvta.to.shared.u64 t, %1; cvt.u32.u64 %0, t; }" : "=r"(a) : "l"(p));
    return a;
}
static __device__ __forceinline__ uint32_t f2tf32(float x) {
    uint32_t r; asm("cvt.rna.tf32.f32 %0, %1;" : "=r"(r) : "f"(x)); return r;
}
static __device__ __forceinline__ void ldsm4(uint32_t& r0, uint32_t& r1,
                                             uint32_t& r2, uint32_t& r3, uint32_t addr) {
    asm volatile("ldmatrix.sync.aligned.m8n8.x4.shared.b16 {%0,%1,%2,%3}, [%4];"
                 : "=r"(r0), "=r"(r1), "=r"(r2), "=r"(r3) : "r"(addr));
}
static __device__ __forceinline__ void mma_tf32(float c[4],
                                                uint32_t a0, uint32_t a1, uint32_t a2, uint32_t a3,
                                                uint32_t b0, uint32_t b1) {
    asm volatile(
        "mma.sync.aligned.m16n8k8.row.col.f32.tf32.tf32.f32 "
        "{%0,%1,%2,%3}, {%4,%5,%6,%7}, {%8,%9}, {%0,%1,%2,%3};\n"
        : "+f"(c[0]), "+f"(c[1]), "+f"(c[2]), "+f"(c[3])
        : "r"(a0), "r"(a1), "r"(a2), "r"(a3), "r"(b0), "r"(b1));
}

__global__ void __launch_bounds__(NT, 1)
bsl_ldsm(const float* __restrict__ X, const float* __restrict__ W,
         const float* __restrict__ Bias, float* __restrict__ Y) {
    const int K = 4096, N = 4096;
    extern __shared__ uint32_t sm[];
    // As: [2][BM*BK] words, Bs: [2][BN*BK] words
    const uint32_t sbase  = s2u(sm);
    const uint32_t AsByte = sbase;
    const uint32_t BsByte = sbase + 2u * BM * BK * 4u;

    const int tid  = threadIdx.x;
    const int lane = tid & 31;
    const int warp = tid >> 5;
    const int wm   = warp >> 2;          // 0..3 (M, 64 rows each)
    const int wn   = warp & 3;           // 0..3 (N, 32 cols each)

    const int bm = blockIdx.y * BM;
    const int bn = blockIdx.x * BN;

    // ---- producer mapping: 8 threads per 128B row
    const int arow = tid >> 3;           // 0..63
    const int kq   = tid & 7;            // quad within row
    const float* Ag = X + (size_t)(bm + arow) * K + kq * 4;
    const float* Wg = W + (size_t)(bn + arow) * K + kq * 4;
    // swizzled STS word offsets (m&7 == arow&7 for all row strides of 64)
    const int swq = (kq * 4) ^ ((arow & 7) * 4);
    int sA[4], sB[2];
    #pragma unroll
    for (int i = 0; i < 4; ++i) sA[i] = (arow + i * 64) * BK + swq;
    #pragma unroll
    for (int j = 0; j < 2; ++j) sB[j] = (arow + j * 64) * BK + swq;

    // ---- ldmatrix per-thread addressing
    const int g = lane >> 3, r = lane & 7;
    uint32_t aoff[4], boff[2];
    #pragma unroll
    for (int mt = 0; mt < 4; ++mt)
        aoff[mt] = (uint32_t)((wm * 64 + mt * 16 + (g & 1) * 8 + r) * 128);
    #pragma unroll
    for (int ntp = 0; ntp < 2; ++ntp)
        boff[ntp] = (uint32_t)((wn * 32 + (2 * ntp + (g >> 1)) * 8 + r) * 128);
    const int ga = g >> 1;   // A quad select
    const int gb = g & 1;    // B quad select

    float acc[4][4][4];
    #pragma unroll
    for (int mt = 0; mt < 4; ++mt)
        #pragma unroll
        for (int nt = 0; nt < 4; ++nt)
            #pragma unroll
            for (int j = 0; j < 4; ++j) acc[mt][nt][j] = 0.0f;

    float4 ra[4], rb[2];
    const int nk = K / BK;               // 128

    // prologue: stage 0
    #pragma unroll
    for (int i = 0; i < 4; ++i) ra[i] = *(const float4*)(Ag + (size_t)(i * 64) * K);
    #pragma unroll
    for (int j = 0; j < 2; ++j) rb[j] = *(const float4*)(Wg + (size_t)(j * 64) * K);
    #pragma unroll
    for (int i = 0; i < 4; ++i) {
        uint4 u = { f2tf32(ra[i].x), f2tf32(ra[i].y), f2tf32(ra[i].z), f2tf32(ra[i].w) };
        *(uint4*)(sm + sA[i]) = u;
    }
    #pragma unroll
    for (int j = 0; j < 2; ++j) {
        uint4 u = { f2tf32(rb[j].x), f2tf32(rb[j].y), f2tf32(rb[j].z), f2tf32(rb[j].w) };
        *(uint4*)(sm + 2 * BM * BK + sB[j]) = u;
    }
    __syncthreads();

    int cur = 0;
    for (int t = 0; t < nk; ++t) {
        if (t + 1 < nk) {
            const float* Ap = Ag + (size_t)(t + 1) * BK;
            const float* Wp = Wg + (size_t)(t + 1) * BK;
            #pragma unroll
            for (int i = 0; i < 4; ++i) ra[i] = *(const float4*)(Ap + (size_t)(i * 64) * K);
            #pragma unroll
            for (int j = 0; j < 2; ++j) rb[j] = *(const float4*)(Wp + (size_t)(j * 64) * K);
        }

        const uint32_t Ab = AsByte + (uint32_t)cur * (BM * BK * 4);
        const uint32_t Bb = BsByte + (uint32_t)cur * (BN * BK * 4);
        #pragma unroll
        for (int kk = 0; kk < 4; ++kk) {
            const uint32_t qxA = (uint32_t)((((2 * kk + ga) ^ r)) * 16);
            const uint32_t qxB = (uint32_t)((((2 * kk + gb) ^ r)) * 16);
            uint32_t a[4][4], b[4][2];
            #pragma unroll
            for (int mt = 0; mt < 4; ++mt)
                ldsm4(a[mt][0], a[mt][1], a[mt][2], a[mt][3], Ab + aoff[mt] + qxA);
            #pragma unroll
            for (int ntp = 0; ntp < 2; ++ntp)
                ldsm4(b[2 * ntp][0], b[2 * ntp][1], b[2 * ntp + 1][0], b[2 * ntp + 1][1],
                      Bb + boff[ntp] + qxB);
            #pragma unroll
            for (int mt = 0; mt < 4; ++mt)
                #pragma unroll
                for (int nt = 0; nt < 4; ++nt)
                    mma_tf32(acc[mt][nt],
                             a[mt][0], a[mt][1], a[mt][2], a[mt][3],
                             b[nt][0], b[nt][1]);
        }

        if (t + 1 < nk) {
            uint32_t* Asn = sm + (cur ^ 1) * (BM * BK);
            uint32_t* Bsn = sm + 2 * BM * BK + (cur ^ 1) * (BN * BK);
            #pragma unroll
            for (int i = 0; i < 4; ++i) {
                uint4 u = { f2tf32(ra[i].x), f2tf32(ra[i].y), f2tf32(ra[i].z), f2tf32(ra[i].w) };
                *(uint4*)(Asn + sA[i]) = u;
            }
            #pragma unroll
            for (int j = 0; j < 2; ++j) {
                uint4 u = { f2tf32(rb[j].x), f2tf32(rb[j].y), f2tf32(rb[j].z), f2tf32(rb[j].w) };
                *(uint4*)(Bsn + sB[j]) = u;
            }
        }
        __syncthreads();
        cur ^= 1;
    }

    // ---- epilogue: bias + fp32 store
    const int row = lane >> 2;
    const int col = lane & 3;
    #pragma unroll
    for (int nt = 0; nt < 4; ++nt) {
        const int gn = bn + wn * 32 + nt * 8 + col * 2;
        const float2 bb = *(const float2*)(Bias + gn);
        #pragma unroll
        for (int mt = 0; mt < 4; ++mt) {
            const int gm = bm + wm * 64 + mt * 16 + row;
            float2 v0, v1;
            v0.x = acc[mt][nt][0] + bb.x; v0.y = acc[mt][nt][1] + bb.y;
            v1.x = acc[mt][nt][2] + bb.x; v1.y = acc[mt][nt][3] + bb.y;
            *(float2*)(Y + (size_t)gm * N + gn)       = v0;
            *(float2*)(Y + (size_t)(gm + 8) * N + gn) = v1;
        }
    }
}

extern "C" void kernel_launch(void* const* d_in, const int* in_sizes, int n_in,
                              void* d_out, int out_size) {
    const float* X    = (const float*)d_in[0];   // [M, 4096]
    const float* W    = (const float*)d_in[1];   // [4096, 4096]
    const float* Bias = (const float*)d_in[2];   // [4096]
    float* Y = (float*)d_out;

    const int K = 4096;
    const int M = in_sizes[0] / K;               // 8192

    const size_t smem_bytes = (size_t)(2 * BM * BK + 2 * BN * BK) * 4; // 98304
    cudaFuncSetAttribute(bsl_ldsm, cudaFuncAttributeMaxDynamicSharedMemorySize,
                         (int)smem_bytes);

    dim3 grid(4096 / BN, M / BM);   // (32, 32), N fast for L2 reuse
    bsl_ldsm<<<grid, NT, smem_bytes>>>(X, W, Bias, Y);
}